// round 9
// baseline (speedup 1.0000x reference)
#include <cuda_runtime.h>
#include <math.h>

#define BS 8
#define NP 2048
#define CD 12
#define FD 2
#define DD 24
#define KS 16
#define RPB 8
#define TPB 512
#define MPT 4
#define CAP 64
#define FULLMASK 0xffffffffu

typedef unsigned long long ull;

// normalized features, d-major for coalesced m-loads: gFnT[b][d][m]
__device__ float gFnT[BS][DD][NP];

// ---------------------------------------------------------------------------
// prep: normalized features (reference fp32 arithmetic order) + tgt_out copy.
// ---------------------------------------------------------------------------
__global__ void prep_kernel(const float* __restrict__ x, const int* __restrict__ flowp,
                            float* __restrict__ out) {
    int idx = blockIdx.x * blockDim.x + threadIdx.x;
    if (idx >= BS * NP) return;
    int b = idx >> 11;
    int n = idx & (NP - 1);
    int flow = flowp ? flowp[0] : 0;
    const float* xb = x + (size_t)b * (CD * FD * NP);

    float feats[DD];
#pragma unroll
    for (int f = 0; f < FD; f++)
#pragma unroll
        for (int c = 0; c < CD; c++)
            feats[f * CD + c] = xb[(c * FD + f) * NP + n];

    float ss = 0.f;
#pragma unroll
    for (int d = 0; d < DD; d++) ss = __fadd_rn(ss, __fmul_rn(feats[d], feats[d]));
    float denom = __fadd_rn(sqrtf(ss), 1e-8f);
#pragma unroll
    for (int d = 0; d < DD; d++)
        gFnT[b][d][n] = __fdiv_rn(feats[d], denom);

    float* out2 = out + (size_t)BS * NP * KS * CD;
#pragma unroll
    for (int c = 0; c < CD; c++)
        out2[(b * CD + c) * NP + n] = xb[(c * FD + flow) * NP + n];
}

// orderable 64-bit key: (monotone float map) desc, then index asc
__device__ __forceinline__ ull make_key(float v, int idx) {
    unsigned u = __float_as_uint(v);
    u = (u & 0x80000000u) ? ~u : (u | 0x80000000u);
    return ((ull)u << 32) | (unsigned)(NP - 1 - idx);
}
__device__ __forceinline__ int key_idx(ull k) {
    return NP - 1 - (int)(k & 0xffffffffu);
}

// full bitonic sort of 32 keys, descending (lane 0 = largest)
template <typename T_>
__device__ __forceinline__ T_ sort32_desc(T_ v, int lane) {
#pragma unroll
    for (int k2 = 2; k2 <= 32; k2 <<= 1) {
#pragma unroll
        for (int j2 = k2 >> 1; j2 > 0; j2 >>= 1) {
            T_ o = __shfl_xor_sync(FULLMASK, v, j2);
            bool up = ((lane & k2) == 0);
            bool low = ((lane & j2) == 0);
            T_ mx = v > o ? v : o, mn = v > o ? o : v;
            v = (up == low) ? mx : mn;
        }
    }
    return v;
}

// merge: best (desc-sorted) with ch (desc-sorted) -> top-32 of union, desc
__device__ __forceinline__ ull merge32_desc(ull best, ull ch, int lane) {
    ull o = __shfl_sync(FULLMASK, ch, 31 - lane);
    ull v = best > o ? best : o;
#pragma unroll
    for (int j2 = 16; j2 > 0; j2 >>= 1) {
        ull w = __shfl_xor_sync(FULLMASK, v, j2);
        bool low = ((lane & j2) == 0);
        ull mx = v > w ? v : w, mn = v > w ? w : v;
        v = low ? mx : mn;
    }
    return v;
}

// ---------------------------------------------------------------------------
// main: 512 thr, 8 rows, fully register-resident scores (no s_A).
// Phase 1: scalar register dots (R5 form), acc stays in registers.
// Phase 2: 2a per-(warp,row) chunk top-2 via paired shfl reduce;
//          2b warp-per-row threshold = 16th largest of the 32 chunk-top2;
//          2c register compaction via per-row atomics;
//          2d warp-per-row exact u64-key sort; gather on all 16 warps.
// ---------------------------------------------------------------------------
__global__ void __launch_bounds__(TPB, 2) main_kernel(const float* __restrict__ x,
                                                      const int* __restrict__ flowp,
                                                      float* __restrict__ out) {
    __shared__ float s_q[DD * RPB];       // [d][r]
    __shared__ float s_t2[RPB][32];       // per-chunk top-2: [r][2*w + {0,1}]
    __shared__ float s_T[RPB];
    __shared__ int   s_cnt[RPB];
    __shared__ ull   s_ck[RPB][CAP];
    __shared__ int   s_sel[RPB][KS];

    int blk = blockIdx.x;                  // BS * (NP/RPB) = 2048
    int b   = blk >> 8;
    int n0  = (blk & 255) * RPB;
    int tid = threadIdx.x;
    int wid = tid >> 5, lane = tid & 31;

    if (tid < DD * RPB) {
        int d = tid >> 3, r = tid & 7;
        s_q[tid] = gFnT[b][d][n0 + r];
    }
    if (tid < RPB) s_cnt[tid] = 0;
    __syncthreads();

    // ---------------- phase 1: dots (m = 4*tid + j), register-resident -----
    float acc[RPB][MPT];
#pragma unroll
    for (int r = 0; r < RPB; r++)
#pragma unroll
        for (int j = 0; j < MPT; j++) acc[r][j] = 0.f;

#pragma unroll 6
    for (int d = 0; d < DD; d++) {
        float4 fm = reinterpret_cast<const float4*>(&gFnT[b][d][0])[tid];
        float4 qa = *reinterpret_cast<const float4*>(&s_q[d * 8]);
        float4 qb = *reinterpret_cast<const float4*>(&s_q[d * 8 + 4]);
        float q[RPB] = {qa.x, qa.y, qa.z, qa.w, qb.x, qb.y, qb.z, qb.w};
        float f[MPT] = {fm.x, fm.y, fm.z, fm.w};
#pragma unroll
        for (int r = 0; r < RPB; r++)
#pragma unroll
            for (int j = 0; j < MPT; j++)
                acc[r][j] = fmaf(q[r], f[j], acc[r][j]);
    }

    // ---------------- phase 2a: per-(warp,row) chunk top-2 ----------------
#pragma unroll
    for (int r = 0; r < RPB; r++) {
        // top-2 of this thread's 4 values
        float a = fmaxf(acc[r][0], acc[r][1]), bl = fminf(acc[r][0], acc[r][1]);
        float c = fmaxf(acc[r][2], acc[r][3]), dl = fminf(acc[r][2], acc[r][3]);
        float m1 = fmaxf(a, c);
        float m2 = fmaxf(fminf(a, c), fmaxf(bl, dl));
        // 5-stage warp top-2 merge
#pragma unroll
        for (int off = 16; off > 0; off >>= 1) {
            float o1 = __shfl_xor_sync(FULLMASK, m1, off);
            float o2 = __shfl_xor_sync(FULLMASK, m2, off);
            float nm1 = fmaxf(m1, o1);
            float nm2 = fmaxf(fminf(m1, o1), fmaxf(m2, o2));
            m1 = nm1; m2 = nm2;
        }
        if (lane == 0) {
            s_t2[r][2 * wid]     = m1;
            s_t2[r][2 * wid + 1] = m2;
        }
    }
    __syncthreads();

    // ---------------- phase 2b: warp-per-row threshold ----------------
    if (wid < RPB) {
        float v = s_t2[wid][lane];
        v = sort32_desc(v, lane);
        if (lane == 15) s_T[wid] = v;   // 16th largest of chunk top-2 values
    }
    __syncthreads();

    // ---------------- phase 2c: register compaction ----------------
#pragma unroll
    for (int r = 0; r < RPB; r++) {
        float T = s_T[r];
#pragma unroll
        for (int j = 0; j < MPT; j++) {
            if (acc[r][j] >= T) {
                int pos = atomicAdd(&s_cnt[r], 1);
                if (pos < CAP) s_ck[r][pos] = make_key(acc[r][j], 4 * tid + j);
            }
        }
    }
    __syncthreads();

    // ---------------- phase 2d: warp-per-row exact top-16 ----------------
    if (wid < RPB) {
        int r = wid;
        int cnt = s_cnt[r];

        ull best;
        if (cnt <= CAP) {
            ull k0 = (lane < cnt) ? s_ck[r][lane] : 0ULL;
            best = sort32_desc(k0, lane);
            if (cnt > 32) {
                int i = 32 + lane;
                ull kc = (i < cnt) ? s_ck[r][i] : 0ULL;
                kc = sort32_desc(kc, lane);
                best = merge32_desc(best, kc, lane);
            }
        } else {
            // cold exact fallback: recompute scores, chunk-merge full row
            float vv = 0.f;
#pragma unroll
            for (int d = 0; d < DD; d++)
                vv = fmaf(s_q[d * 8 + r], gFnT[b][d][lane], vv);
            best = sort32_desc(make_key(vv, lane), lane);
            for (int c0 = 32; c0 < NP; c0 += 32) {
                int i = c0 + lane;
                float v2 = 0.f;
#pragma unroll
                for (int d = 0; d < DD; d++)
                    v2 = fmaf(s_q[d * 8 + r], gFnT[b][d][i], v2);
                ull kc = sort32_desc(make_key(v2, i), lane);
                best = merge32_desc(best, kc, lane);
            }
        }

        if (lane < KS) s_sel[r][lane] = key_idx(best);
    }
    __syncthreads();

    // ---------------- gather: all 16 warps, half-row each ----------------
    {
        int r = wid & 7, h = wid >> 3;
        int n = n0 + r;
        int flow = flowp ? flowp[0] : 0;
        const float* xb = x + (size_t)b * (CD * FD * NP);
        float* o1 = out + (size_t)(b * NP + n) * (KS * CD);
#pragma unroll
        for (int u = 0; u < 3; u++) {
            int t = h * 96 + u * 32 + lane;    // KS*CD = 192 = 2*96
            int k = t / CD;
            int c = t - k * CD;
            int m = s_sel[r][k];
            o1[t] = xb[(c * FD + flow) * NP + m];
        }
    }
}

extern "C" void kernel_launch(void* const* d_in, const int* in_sizes, int n_in,
                              void* d_out, int out_size) {
    const float* x = (const float*)d_in[0];
    const int* flowp = (n_in >= 2) ? (const int*)d_in[1] : nullptr;
    float* out = (float*)d_out;

    prep_kernel<<<(BS * NP + 255) / 256, 256>>>(x, flowp, out);
    main_kernel<<<BS * (NP / RPB), TPB>>>(x, flowp, out);
}

// round 11
// speedup vs baseline: 1.6442x; 1.6442x over previous
#include <cuda_runtime.h>
#include <math.h>

#define BS 8
#define NP 2048
#define CD 12
#define FD 2
#define DD 24
#define KS 16
#define RPB 8
#define TPB 512
#define MPT 4
#define CAP 64
#define FULLMASK 0xffffffffu

typedef unsigned long long ull;

// smem words: s_ck (RPB*CAP ull) | s_q | s_A | s_T | s_cnt | s_sel
#define SMEM_WORDS (2*RPB*CAP + DD*RPB + RPB*NP + 2*RPB + RPB + RPB*KS)
#define SMEM_BYTES (SMEM_WORDS * 4)

// normalized features, d-major for coalesced m-loads: gFnT[b][d][m]
__device__ float gFnT[BS][DD][NP];

// ---------------------------------------------------------------------------
// prep: normalized features (reference fp32 arithmetic order) + tgt_out copy.
// ---------------------------------------------------------------------------
__global__ void prep_kernel(const float* __restrict__ x, const int* __restrict__ flowp,
                            float* __restrict__ out) {
    int idx = blockIdx.x * blockDim.x + threadIdx.x;
    if (idx >= BS * NP) return;
    int b = idx >> 11;
    int n = idx & (NP - 1);
    int flow = flowp ? flowp[0] : 0;
    const float* xb = x + (size_t)b * (CD * FD * NP);

    float feats[DD];
#pragma unroll
    for (int f = 0; f < FD; f++)
#pragma unroll
        for (int c = 0; c < CD; c++)
            feats[f * CD + c] = xb[(c * FD + f) * NP + n];

    float ss = 0.f;
#pragma unroll
    for (int d = 0; d < DD; d++) ss = __fadd_rn(ss, __fmul_rn(feats[d], feats[d]));
    float denom = __fadd_rn(sqrtf(ss), 1e-8f);
#pragma unroll
    for (int d = 0; d < DD; d++)
        gFnT[b][d][n] = __fdiv_rn(feats[d], denom);

    float* out2 = out + (size_t)BS * NP * KS * CD;
#pragma unroll
    for (int c = 0; c < CD; c++)
        out2[(b * CD + c) * NP + n] = xb[(c * FD + flow) * NP + n];
}

// orderable 64-bit key: (monotone float map) desc, then index asc
__device__ __forceinline__ ull make_key(float v, int idx) {
    unsigned u = __float_as_uint(v);
    u = (u & 0x80000000u) ? ~u : (u | 0x80000000u);
    return ((ull)u << 32) | (unsigned)(NP - 1 - idx);
}
__device__ __forceinline__ int key_idx(ull k) {
    return NP - 1 - (int)(k & 0xffffffffu);
}

// full bitonic sort of 32 keys, descending (lane 0 = largest)
template <typename T_>
__device__ __forceinline__ T_ sort32_desc(T_ v, int lane) {
#pragma unroll
    for (int k2 = 2; k2 <= 32; k2 <<= 1) {
#pragma unroll
        for (int j2 = k2 >> 1; j2 > 0; j2 >>= 1) {
            T_ o = __shfl_xor_sync(FULLMASK, v, j2);
            bool up = ((lane & k2) == 0);
            bool low = ((lane & j2) == 0);
            T_ mx = v > o ? v : o, mn = v > o ? o : v;
            v = (up == low) ? mx : mn;
        }
    }
    return v;
}

// merge: best (desc-sorted) with ch (desc-sorted) -> top-32 of union, desc
__device__ __forceinline__ ull merge32_desc(ull best, ull ch, int lane) {
    ull o = __shfl_sync(FULLMASK, ch, 31 - lane);
    ull v = best > o ? best : o;
#pragma unroll
    for (int j2 = 16; j2 > 0; j2 >>= 1) {
        ull w = __shfl_xor_sync(FULLMASK, v, j2);
        bool low = ((lane & j2) == 0);
        ull mx = v > w ? v : w, mn = v > w ? w : v;
        v = low ? mx : mn;
    }
    return v;
}

// ---------------------------------------------------------------------------
// main: 512 thr, 8 rows. Phase 1: scalar register dots -> s_A (f32).
// Phase 2: warp (r,h) handles half h of row r: lane-max + bitonic threshold
// per half; T = max of halves; register-resident compaction to u64 keys via
// per-row atomics; then BOTH warps of a row rank the <=64 survivors straight
// from smem (no shuffles) and scatter-write the exact ordered top-16.
// ---------------------------------------------------------------------------
__global__ void __launch_bounds__(TPB, 2) main_kernel(const float* __restrict__ x,
                                                      const int* __restrict__ flowp,
                                                      float* __restrict__ out) {
    extern __shared__ float sm[];
    ull*   s_ck  = (ull*)sm;                      // [RPB][CAP] candidate keys
    float* s_q   = (float*)(s_ck + RPB * CAP);    // [DD][RPB]
    float* s_A   = s_q + DD * RPB;                // [RPB][NP]
    float* s_T   = s_A + RPB * NP;                // [RPB][2]
    int*   s_cnt = (int*)(s_T + RPB * 2);         // [RPB]
    int*   s_sel = s_cnt + RPB;                   // [RPB][KS]

    int blk = blockIdx.x;                  // BS * (NP/RPB) = 2048
    int b   = blk >> 8;
    int n0  = (blk & 255) * RPB;
    int tid = threadIdx.x;
    int wid = tid >> 5, lane = tid & 31;

    if (tid < DD * RPB) {
        int d = tid >> 3, r = tid & 7;
        s_q[tid] = gFnT[b][d][n0 + r];
    }
    if (tid < RPB) s_cnt[tid] = 0;
    __syncthreads();

    // ---------------- phase 1: dots (m = 4*tid + j) ----------------
    float acc[RPB][MPT];
#pragma unroll
    for (int r = 0; r < RPB; r++)
#pragma unroll
        for (int j = 0; j < MPT; j++) acc[r][j] = 0.f;

#pragma unroll 6
    for (int d = 0; d < DD; d++) {
        float4 fm = reinterpret_cast<const float4*>(&gFnT[b][d][0])[tid];
        float4 qa = *reinterpret_cast<const float4*>(&s_q[d * 8]);
        float4 qb = *reinterpret_cast<const float4*>(&s_q[d * 8 + 4]);
        float q[RPB] = {qa.x, qa.y, qa.z, qa.w, qb.x, qb.y, qb.z, qb.w};
        float f[MPT] = {fm.x, fm.y, fm.z, fm.w};
#pragma unroll
        for (int r = 0; r < RPB; r++)
#pragma unroll
            for (int j = 0; j < MPT; j++)
                acc[r][j] = fmaf(q[r], f[j], acc[r][j]);
    }

#pragma unroll
    for (int r = 0; r < RPB; r++)
        reinterpret_cast<float4*>(s_A + r * NP)[tid] =
            make_float4(acc[r][0], acc[r][1], acc[r][2], acc[r][3]);
    __syncthreads();

    // ---------------- phase 2a: per-half lane-max + threshold ----------------
    int r = wid & 7, h = wid >> 3;
    const float4* Ar4 = reinterpret_cast<const float4*>(s_A + r * NP);
    int base4 = h * 256 + lane;            // float4 index of this lane's first group

    float4 v[8];
#pragma unroll
    for (int j = 0; j < 8; j++) v[j] = Ar4[base4 + 32 * j];

    float lmax = -INFINITY;
#pragma unroll
    for (int j = 0; j < 8; j++)
        lmax = fmaxf(lmax, fmaxf(fmaxf(v[j].x, v[j].y), fmaxf(v[j].z, v[j].w)));

    float sv = sort32_desc(lmax, lane);
    if (lane == 15) s_T[r * 2 + h] = sv;   // 16th-largest lane-max of this half
    __syncthreads();

    // ---------------- phase 2b: compaction (register-resident values) -------
    {
        float T = fmaxf(s_T[r * 2], s_T[r * 2 + 1]);
        ull* ck = s_ck + r * CAP;
#pragma unroll
        for (int j = 0; j < 8; j++) {
            int mbase = 4 * (base4 + 32 * j);
            float vc[4] = {v[j].x, v[j].y, v[j].z, v[j].w};
#pragma unroll
            for (int c = 0; c < 4; c++) {
                if (vc[c] >= T) {
                    int pos = atomicAdd(&s_cnt[r], 1);
                    if (pos < CAP) ck[pos] = make_key(vc[c], mbase + c);
                }
            }
        }
    }
    __syncthreads();

    // ---------------- phase 2c: rank-based exact top-16 (no shuffles) -------
    {
        int cnt = s_cnt[r];
        ull* ck = s_ck + r * CAP;

        if (cnt <= CAP) {
            // warp h ranks survivors [h*32, h*32+32); both warps of row r work
            int i = h * 32 + lane;
            if (i < cnt) {
                ull ki = ck[i];
                int rank = 0;
                for (int j = 0; j < cnt; j++)
                    rank += (ck[j] > ki);
                if (rank < KS) s_sel[r * KS + rank] = key_idx(ki);
            }
        } else if (h == 0) {
            // cold exact fallback: chunk-merge sort over the full row
            const float* Ar = s_A + r * NP;
            ull best = sort32_desc(make_key(Ar[lane], lane), lane);
            for (int c0 = 32; c0 < NP; c0 += 32) {
                int i2 = c0 + lane;
                ull kc = sort32_desc(make_key(Ar[i2], i2), lane);
                best = merge32_desc(best, kc, lane);
            }
            if (lane < KS) s_sel[r * KS + lane] = key_idx(best);
        }
    }
    __syncthreads();

    // ---------------- gather: all 16 warps, half-row each ----------------
    {
        int n = n0 + r;
        int flow = flowp ? flowp[0] : 0;
        const float* xb = x + (size_t)b * (CD * FD * NP);
        float* o1 = out + (size_t)(b * NP + n) * (KS * CD);
#pragma unroll
        for (int u = 0; u < 3; u++) {
            int t = h * 96 + u * 32 + lane;    // KS*CD = 192 = 2*96
            int k = t / CD;
            int c = t - k * CD;
            int m = s_sel[r * KS + k];
            o1[t] = xb[(c * FD + flow) * NP + m];
        }
    }
}

extern "C" void kernel_launch(void* const* d_in, const int* in_sizes, int n_in,
                              void* d_out, int out_size) {
    const float* x = (const float*)d_in[0];
    const int* flowp = (n_in >= 2) ? (const int*)d_in[1] : nullptr;
    float* out = (float*)d_out;

    prep_kernel<<<(BS * NP + 255) / 256, 256>>>(x, flowp, out);

    cudaFuncSetAttribute(main_kernel, cudaFuncAttributeMaxDynamicSharedMemorySize, SMEM_BYTES);
    main_kernel<<<BS * (NP / RPB), TPB, SMEM_BYTES>>>(x, flowp, out);
}